// round 15
// baseline (speedup 1.0000x reference)
#include <cuda_runtime.h>
#include <cuda_bf16.h>
#include <mma.h>
#include <cstdint>

using namespace nvcuda;

// Problem constants (N=50000, E=800000, D=HID=128, K=3)
#define MAXN 50000
#define MAXE 800000
#define D 128
#define SCAN_B 256
#define MAXBLK ((MAXN + SCAN_B - 1) / SCAN_B)   // 196

// ---------------- scratch (no allocs allowed -> __device__ globals) ----------------
__device__ float g_T1[MAXN * D];
__device__ float g_P [MAXN * D];
__device__ float g_Ha[MAXN * D];
__device__ float g_Hb[MAXN * D];
__device__ __nv_bfloat16 g_Wbhi[3][3 * D * D];  // per-layer combined weight [384][128], bf16 hi
__device__ __nv_bfloat16 g_Wblo[3][3 * D * D];  // bf16 lo (residual)
__device__ float g_dinv[MAXN];
__device__ int   g_cnt   [MAXN];
__device__ int   g_rowptr[MAXN + 1];
__device__ int   g_cur   [MAXN];
__device__ int2  g_ecw   [MAXE];   // packed CSR edge: .x = col, .y = weight bits
__device__ int   g_bsum  [MAXBLK];

// ---------------- CSR build (unchanged, validated) ----------------
__global__ void zero_int_kernel(int* __restrict__ p, int n) {
    int i = blockIdx.x * blockDim.x + threadIdx.x;
    if (i < n) p[i] = 0;
}

__global__ void hist_kernel(const int* __restrict__ row, const int* __restrict__ col,
                            int* __restrict__ cnt, int E) {
    int e = blockIdx.x * blockDim.x + threadIdx.x;
    if (e < E) {
        int r = row[e], c = col[e];
        if (r != c) atomicAdd(&cnt[r], 1);
    }
}

__global__ void dinv_kernel(const int* __restrict__ cnt, float* __restrict__ dinv, int n) {
    int i = blockIdx.x * blockDim.x + threadIdx.x;
    if (i < n) {
        int d = cnt[i];
        dinv[i] = (d > 0) ? rsqrtf((float)d) : 0.f;
    }
}

__global__ __launch_bounds__(SCAN_B) void scan_sum_kernel(
    const int* __restrict__ cnt, int* __restrict__ bsum, int N)
{
    __shared__ int wsum[SCAN_B / 32];
    int i = blockIdx.x * SCAN_B + threadIdx.x;
    int v = (i < N) ? cnt[i] : 0;
    int lane = threadIdx.x & 31, w = threadIdx.x >> 5;
#pragma unroll
    for (int o = 16; o > 0; o >>= 1) v += __shfl_down_sync(~0u, v, o);
    if (lane == 0) wsum[w] = v;
    __syncthreads();
    if (threadIdx.x == 0) {
        int s = 0;
#pragma unroll
        for (int j = 0; j < SCAN_B / 32; j++) s += wsum[j];
        bsum[blockIdx.x] = s;
    }
}

__global__ __launch_bounds__(256) void scan_partials_kernel(int* __restrict__ bsum, int nblk)
{
    __shared__ int woff[8];
    int t = threadIdx.x;
    int v = (t < nblk) ? bsum[t] : 0;
    int lane = t & 31, w = t >> 5;
    int x = v;
#pragma unroll
    for (int o = 1; o < 32; o <<= 1) {
        int y = __shfl_up_sync(~0u, x, o);
        if (lane >= o) x += y;
    }
    if (lane == 31) woff[w] = x;
    __syncthreads();
    if (t == 0) {
        int run = 0;
#pragma unroll
        for (int j = 0; j < 8; j++) { int tmp = woff[j]; woff[j] = run; run += tmp; }
    }
    __syncthreads();
    int excl = x - v + woff[w];
    if (t < nblk) bsum[t] = excl;
}

__global__ __launch_bounds__(SCAN_B) void scan_write_kernel(
    const int* __restrict__ cnt, const int* __restrict__ bsum,
    int* __restrict__ rowptr, int* __restrict__ cur, int N)
{
    __shared__ int woff[SCAN_B / 32];
    int t = threadIdx.x;
    int i = blockIdx.x * SCAN_B + t;
    int v = (i < N) ? cnt[i] : 0;
    int lane = t & 31, w = t >> 5;
    int x = v;
#pragma unroll
    for (int o = 1; o < 32; o <<= 1) {
        int y = __shfl_up_sync(~0u, x, o);
        if (lane >= o) x += y;
    }
    if (lane == 31) woff[w] = x;
    __syncthreads();
    if (t == 0) {
        int run = 0;
#pragma unroll
        for (int j = 0; j < SCAN_B / 32; j++) { int tmp = woff[j]; woff[j] = run; run += tmp; }
    }
    __syncthreads();
    int excl = x - v + woff[w] + bsum[blockIdx.x];
    if (i < N) { rowptr[i] = excl; cur[i] = excl; }
    if (i == N - 1) rowptr[N] = excl + v;
}

__global__ void scatter_kernel(const int* __restrict__ row, const int* __restrict__ col,
                               const float* __restrict__ dinv,
                               int* __restrict__ cur, int2* __restrict__ ecw, int E)
{
    int e = blockIdx.x * blockDim.x + threadIdx.x;
    if (e < E) {
        int r = row[e], c = col[e];
        if (r != c) {
            int pos = atomicAdd(&cur[r], 1);
            float w = -dinv[r] * dinv[c];
            ecw[pos] = make_int2(c, __float_as_int(w));
        }
    }
}

// Combined weight [gk][n], gk = p*128 + din: {W0-W2, W1, 2*W2}; bf16 hi/lo, all 3 layers.
__global__ void prep_wbf_all_kernel(const float* __restrict__ Wa, const float* __restrict__ Wb,
                                    const float* __restrict__ Wc,
                                    __nv_bfloat16* __restrict__ Bhi,
                                    __nv_bfloat16* __restrict__ Blo) {
    int t = blockIdx.x * blockDim.x + threadIdx.x;   // over 3 * 384*128
    if (t < 3 * 3 * D * D) {
        int layer = t / (3 * D * D);
        int idx   = t % (3 * D * D);
        const float* W = (layer == 0) ? Wa : (layer == 1) ? Wb : Wc;
        int gk = idx / D;
        int n  = idx % D;
        int p  = gk >> 7;
        int din = gk & 127;
        float v;
        if (p == 0)      v = W[din * D + n] - W[2 * D * D + din * D + n];
        else if (p == 1) v = W[D * D + din * D + n];
        else             v = 2.f * W[2 * D * D + din * D + n];
        __nv_bfloat16 hi = __float2bfloat16(v);
        __nv_bfloat16 lo = __float2bfloat16(v - __bfloat162float(hi));
        Bhi[t] = hi;
        Blo[t] = lo;
    }
}

// ---------------- atomic-free propagation (unchanged, validated) ----------------
__global__ __launch_bounds__(256) void prop_csr_kernel(
    const float* __restrict__ src, float* __restrict__ dst,
    const int* __restrict__ rowptr, const int2* __restrict__ ecw, int N)
{
    const int warp = (blockIdx.x * blockDim.x + threadIdx.x) >> 5;
    const int lane = threadIdx.x & 31;
    if (warp >= N) return;

    const int s = __ldg(rowptr + warp);
    const int e = __ldg(rowptr + warp + 1);

    float ax = 0.f, ay = 0.f, az = 0.f, aw = 0.f;
    const int off = lane * 4;

    int i = s;
    for (; i + 3 < e; i += 4) {
        int2 e0 = __ldg(ecw + i);
        int2 e1 = __ldg(ecw + i + 1);
        int2 e2 = __ldg(ecw + i + 2);
        int2 e3 = __ldg(ecw + i + 3);
        float4 v0 = *reinterpret_cast<const float4*>(src + (size_t)e0.x * D + off);
        float4 v1 = *reinterpret_cast<const float4*>(src + (size_t)e1.x * D + off);
        float4 v2 = *reinterpret_cast<const float4*>(src + (size_t)e2.x * D + off);
        float4 v3 = *reinterpret_cast<const float4*>(src + (size_t)e3.x * D + off);
        float w0 = __int_as_float(e0.y), w1 = __int_as_float(e1.y);
        float w2 = __int_as_float(e2.y), w3 = __int_as_float(e3.y);
        ax = fmaf(w0, v0.x, ax); ay = fmaf(w0, v0.y, ay);
        az = fmaf(w0, v0.z, az); aw = fmaf(w0, v0.w, aw);
        ax = fmaf(w1, v1.x, ax); ay = fmaf(w1, v1.y, ay);
        az = fmaf(w1, v1.z, az); aw = fmaf(w1, v1.w, aw);
        ax = fmaf(w2, v2.x, ax); ay = fmaf(w2, v2.y, ay);
        az = fmaf(w2, v2.z, az); aw = fmaf(w2, v2.w, aw);
        ax = fmaf(w3, v3.x, ax); ay = fmaf(w3, v3.y, ay);
        az = fmaf(w3, v3.z, az); aw = fmaf(w3, v3.w, aw);
    }
    for (; i < e; ++i) {
        int2 e0 = __ldg(ecw + i);
        float w0 = __int_as_float(e0.y);
        float4 v0 = *reinterpret_cast<const float4*>(src + (size_t)e0.x * D + off);
        ax = fmaf(w0, v0.x, ax); ay = fmaf(w0, v0.y, ay);
        az = fmaf(w0, v0.z, az); aw = fmaf(w0, v0.w, aw);
    }

    *reinterpret_cast<float4*>(dst + (size_t)warp * D + off) = make_float4(ax, ay, az, aw);
}

// ---------------- wmma bf16-split fused triple GEMM + bias + ReLU ----------------
// 256x128 CTA tile, 8 warps, warp = 32 rows x 128 cols (2x8 m16n16k16 frags).
// frag-load:mma ratio 2.4:1 (vs 1:1 at 32x64) -> tensor pipe duty up.
// D = Ahi*Bhi + Ahi*Blo + Alo*Bhi in fp32 accum. 2-stage smem pipeline, 1 sync/chunk.
#define BMROWS 256
#define LDA 40
#define LDB 136
#define LDC 132
#define A_BUF_B (BMROWS * LDA * 2)            // 20480
#define B_BUF_B (32 * LDB * 2)                // 8704
#define STAGE_B (2 * A_BUF_B + 2 * B_BUF_B)   // 58368
#define SM_AHI(s)  ((s) * STAGE_B)
#define SM_ALO(s)  (SM_AHI(s) + A_BUF_B)
#define SM_BHI(s)  (SM_ALO(s) + A_BUF_B)
#define SM_BLO(s)  (SM_BHI(s) + B_BUF_B)
#define SM_AB_END  (2 * STAGE_B)                       // 116736
#define SM_STAGE_BYTES (BMROWS * LDC * 4)              // 135168 (aliases mainloop smem)
#define SM_TOTAL (SM_AB_END > SM_STAGE_BYTES ? SM_AB_END : SM_STAGE_BYTES)

__global__ __launch_bounds__(256, 1) void gemm3_wmma_kernel(
    const float* __restrict__ A0, const float* __restrict__ A1, const float* __restrict__ A2,
    const __nv_bfloat16* __restrict__ Whi, const __nv_bfloat16* __restrict__ Wlo,
    const float* __restrict__ bias, float* __restrict__ out, int nrows)
{
    extern __shared__ char smem[];
    float* sC = reinterpret_cast<float*>(smem);

    const int tid = threadIdx.x;
    const int wid = tid >> 5;          // 0..7: warp rows wid*32 .. +32, all 128 cols
    const int row0 = blockIdx.x * BMROWS;

    // A load mapping: one thread per row, 32 k-cols (8 float4)
    const int grow   = row0 + tid;
    const bool valid = (grow < nrows);
    // B load mapping: row = tid>>3 (0..31), 16 cols at (tid&7)*16
    const int b_row = tid >> 3;
    const int b_c0  = (tid & 7) * 16;

    wmma::fragment<wmma::accumulator, 16, 16, 16, float> acc[2][8];
#pragma unroll
    for (int i = 0; i < 2; i++)
#pragma unroll
        for (int j = 0; j < 8; j++) wmma::fill_fragment(acc[i][j], 0.f);

    float4 ra[8];
    uint4  rb[4];
    auto fetch = [&](int ch) {
        const int part  = ch >> 2;
        const float* A  = (part == 0) ? A0 : (part == 1) ? A1 : A2;
        const int kbase = (ch & 3) * 32;
#pragma unroll
        for (int q = 0; q < 8; ++q) {
            ra[q] = make_float4(0.f, 0.f, 0.f, 0.f);
            if (valid)
                ra[q] = *reinterpret_cast<const float4*>(A + (size_t)grow * D + kbase + q * 4);
        }
        const size_t g = (size_t)(ch * 32 + b_row) * D + b_c0;
        rb[0] = *reinterpret_cast<const uint4*>(Whi + g);
        rb[1] = *reinterpret_cast<const uint4*>(Whi + g + 8);
        rb[2] = *reinterpret_cast<const uint4*>(Wlo + g);
        rb[3] = *reinterpret_cast<const uint4*>(Wlo + g + 8);
    };
    auto stash = [&](int s) {
        __nv_bfloat16* sAhi = reinterpret_cast<__nv_bfloat16*>(smem + SM_AHI(s));
        __nv_bfloat16* sAlo = reinterpret_cast<__nv_bfloat16*>(smem + SM_ALO(s));
        __nv_bfloat16* sBhi = reinterpret_cast<__nv_bfloat16*>(smem + SM_BHI(s));
        __nv_bfloat16* sBlo = reinterpret_cast<__nv_bfloat16*>(smem + SM_BLO(s));
#pragma unroll
        for (int q = 0; q < 8; ++q) {
            float4 v = ra[q];
            __nv_bfloat162 h01 = __floats2bfloat162_rn(v.x, v.y);
            __nv_bfloat162 h23 = __floats2bfloat162_rn(v.z, v.w);
            __nv_bfloat162 l01 = __floats2bfloat162_rn(v.x - __bfloat162float(h01.x),
                                                       v.y - __bfloat162float(h01.y));
            __nv_bfloat162 l23 = __floats2bfloat162_rn(v.z - __bfloat162float(h23.x),
                                                       v.w - __bfloat162float(h23.y));
            *reinterpret_cast<__nv_bfloat162*>(sAhi + tid * LDA + q * 4)     = h01;
            *reinterpret_cast<__nv_bfloat162*>(sAhi + tid * LDA + q * 4 + 2) = h23;
            *reinterpret_cast<__nv_bfloat162*>(sAlo + tid * LDA + q * 4)     = l01;
            *reinterpret_cast<__nv_bfloat162*>(sAlo + tid * LDA + q * 4 + 2) = l23;
        }
        *reinterpret_cast<uint4*>(sBhi + b_row * LDB + b_c0)     = rb[0];
        *reinterpret_cast<uint4*>(sBhi + b_row * LDB + b_c0 + 8) = rb[1];
        *reinterpret_cast<uint4*>(sBlo + b_row * LDB + b_c0)     = rb[2];
        *reinterpret_cast<uint4*>(sBlo + b_row * LDB + b_c0 + 8) = rb[3];
    };

    fetch(0);
    stash(0);
    __syncthreads();

    for (int ch = 0; ch < 12; ++ch) {
        const int cur = ch & 1;
        if (ch + 1 < 12) fetch(ch + 1);   // overlap gmem with mma below

        const __nv_bfloat16* sAhi = reinterpret_cast<const __nv_bfloat16*>(smem + SM_AHI(cur));
        const __nv_bfloat16* sAlo = reinterpret_cast<const __nv_bfloat16*>(smem + SM_ALO(cur));
        const __nv_bfloat16* sBhi = reinterpret_cast<const __nv_bfloat16*>(smem + SM_BHI(cur));
        const __nv_bfloat16* sBlo = reinterpret_cast<const __nv_bfloat16*>(smem + SM_BLO(cur));

#pragma unroll
        for (int k16 = 0; k16 < 2; ++k16) {
            wmma::fragment<wmma::matrix_a, 16, 16, 16, __nv_bfloat16, wmma::row_major> fahi[2], falo[2];
#pragma unroll
            for (int i = 0; i < 2; i++) {
                wmma::load_matrix_sync(fahi[i], sAhi + (wid * 32 + i * 16) * LDA + k16 * 16, LDA);
                wmma::load_matrix_sync(falo[i], sAlo + (wid * 32 + i * 16) * LDA + k16 * 16, LDA);
            }
#pragma unroll
            for (int j = 0; j < 8; j++) {
                wmma::fragment<wmma::matrix_b, 16, 16, 16, __nv_bfloat16, wmma::row_major> fbhi, fblo;
                wmma::load_matrix_sync(fbhi, sBhi + (k16 * 16) * LDB + j * 16, LDB);
                wmma::load_matrix_sync(fblo, sBlo + (k16 * 16) * LDB + j * 16, LDB);
#pragma unroll
                for (int i = 0; i < 2; i++) {
                    wmma::mma_sync(acc[i][j], fahi[i], fbhi, acc[i][j]);
                    wmma::mma_sync(acc[i][j], fahi[i], fblo, acc[i][j]);
                    wmma::mma_sync(acc[i][j], falo[i], fbhi, acc[i][j]);
                }
            }
        }

        if (ch + 1 < 12) {
            stash((ch + 1) & 1);   // writes other buffer; readers above used cur
            __syncthreads();
        }
    }
    __syncthreads();   // all frag reads done before epilogue aliases smem

    // ---- epilogue: stage to smem, then bias + ReLU + coalesced store ----
#pragma unroll
    for (int i = 0; i < 2; i++)
#pragma unroll
        for (int j = 0; j < 8; j++)
            wmma::store_matrix_sync(sC + (wid * 32 + i * 16) * LDC + j * 16,
                                    acc[i][j], LDC, wmma::mem_row_major);
    __syncthreads();

    // one thread per row: 128 cols
    {
        const int r = row0 + tid;
        if (r < nrows) {
            const float* src = sC + tid * LDC;
            float* dst = out + (size_t)r * D;
#pragma unroll
            for (int q = 0; q < 32; ++q) {
                float4 v = *reinterpret_cast<const float4*>(src + q * 4);
                float4 bv = *reinterpret_cast<const float4*>(bias + q * 4);
                v.x = fmaxf(v.x + bv.x, 0.f);
                v.y = fmaxf(v.y + bv.y, 0.f);
                v.z = fmaxf(v.z + bv.z, 0.f);
                v.w = fmaxf(v.w + bv.w, 0.f);
                *reinterpret_cast<float4*>(dst + q * 4) = v;
            }
        }
    }
}

// ---------------- host-side orchestration ----------------
static inline int ceil_div(int a, int b) { return (a + b - 1) / b; }

extern "C" void kernel_launch(void* const* d_in, const int* in_sizes, int n_in,
                              void* d_out, int out_size)
{
    const float* x  = (const float*)d_in[0];
    const int*   ei = (const int*)  d_in[1];
    const float* W1 = (const float*)d_in[2];
    const float* b1 = (const float*)d_in[3];
    const float* W2 = (const float*)d_in[4];
    const float* b2 = (const float*)d_in[5];
    const float* W3 = (const float*)d_in[6];
    const float* b3 = (const float*)d_in[7];
    float* out = (float*)d_out;

    const int N = in_sizes[0] / D;
    const int E = in_sizes[1] / 2;
    const int* row = ei;
    const int* col = ei + E;

    float *T1, *P, *Ha, *Hb, *dinv;
    __nv_bfloat16 (*Whi)[3 * D * D], (*Wlo)[3 * D * D];
    int *cnt, *rowptr, *cur, *bsum;
    int2* ecw;
    cudaGetSymbolAddress((void**)&T1,     g_T1);
    cudaGetSymbolAddress((void**)&P,      g_P);
    cudaGetSymbolAddress((void**)&Ha,     g_Ha);
    cudaGetSymbolAddress((void**)&Hb,     g_Hb);
    cudaGetSymbolAddress((void**)&Whi,    g_Wbhi);
    cudaGetSymbolAddress((void**)&Wlo,    g_Wblo);
    cudaGetSymbolAddress((void**)&dinv,   g_dinv);
    cudaGetSymbolAddress((void**)&cnt,    g_cnt);
    cudaGetSymbolAddress((void**)&rowptr, g_rowptr);
    cudaGetSymbolAddress((void**)&cur,    g_cur);
    cudaGetSymbolAddress((void**)&ecw,    g_ecw);
    cudaGetSymbolAddress((void**)&bsum,   g_bsum);

    cudaFuncSetAttribute(gemm3_wmma_kernel,
                         cudaFuncAttributeMaxDynamicSharedMemorySize, SM_TOTAL);

    const int egrid = ceil_div(E, 256);
    const int ngrid = ceil_div(N, 256);
    const int sgrid = ceil_div(N, SCAN_B);
    const int pgrid = ceil_div(N * 32, 256);
    const int ggrid = ceil_div(N, BMROWS);

    // ---- weight prep (all 3 layers) ----
    prep_wbf_all_kernel<<<ceil_div(3 * 3 * D * D, 256), 256>>>(W1, W2, W3, Whi[0], Wlo[0]);

    // ---- CSR build (once; serves all 6 props) ----
    zero_int_kernel<<<ngrid, 256>>>(cnt, N);
    hist_kernel<<<egrid, 256>>>(row, col, cnt, E);
    dinv_kernel<<<ngrid, 256>>>(cnt, dinv, N);
    scan_sum_kernel<<<sgrid, SCAN_B>>>(cnt, bsum, N);
    scan_partials_kernel<<<1, 256>>>(bsum, sgrid);
    scan_write_kernel<<<sgrid, SCAN_B>>>(cnt, bsum, rowptr, cur, N);
    scatter_kernel<<<egrid, 256>>>(row, col, dinv, cur, ecw, E);

    // ---- layer 1 ----
    prop_csr_kernel<<<pgrid, 256>>>(x,  T1, rowptr, ecw, N);
    prop_csr_kernel<<<pgrid, 256>>>(T1, P,  rowptr, ecw, N);
    gemm3_wmma_kernel<<<ggrid, 256, SM_TOTAL>>>(x, T1, P, Whi[0], Wlo[0], b1, Ha, N);

    // ---- layer 2 ----
    prop_csr_kernel<<<pgrid, 256>>>(Ha, T1, rowptr, ecw, N);
    prop_csr_kernel<<<pgrid, 256>>>(T1, P,  rowptr, ecw, N);
    gemm3_wmma_kernel<<<ggrid, 256, SM_TOTAL>>>(Ha, T1, P, Whi[1], Wlo[1], b2, Hb, N);

    // ---- layer 3 ----
    prop_csr_kernel<<<pgrid, 256>>>(Hb, T1, rowptr, ecw, N);
    prop_csr_kernel<<<pgrid, 256>>>(T1, P,  rowptr, ecw, N);
    gemm3_wmma_kernel<<<ggrid, 256, SM_TOTAL>>>(Hb, T1, P, Whi[2], Wlo[2], b3, out, N);
}

// round 17
// speedup vs baseline: 1.2698x; 1.2698x over previous
#include <cuda_runtime.h>
#include <cuda_bf16.h>
#include <mma.h>
#include <cstdint>

using namespace nvcuda;

// Problem constants (N=50000, E=800000, D=HID=128, K=3)
#define MAXN 50000
#define MAXE 800000
#define D 128
#define SCAN_B 256
#define MAXBLK ((MAXN + SCAN_B - 1) / SCAN_B)   // 196

// ---------------- scratch (no allocs allowed -> __device__ globals) ----------------
__device__ float g_T1[MAXN * D];
__device__ float g_P [MAXN * D];
__device__ float g_Ha[MAXN * D];
__device__ float g_Hb[MAXN * D];
__device__ __nv_bfloat16 g_Wbhi[3][3 * D * D];  // per-layer combined weight [384][128], bf16 hi
__device__ __nv_bfloat16 g_Wblo[3][3 * D * D];  // bf16 lo (residual)
__device__ float g_dinv[MAXN];
__device__ int   g_cnt   [MAXN];
__device__ int   g_rowptr[MAXN + 1];
__device__ int   g_cur   [MAXN];
__device__ int2  g_ecw   [MAXE];   // packed CSR edge: .x = col, .y = weight bits
__device__ int   g_bsum  [MAXBLK];

// ---------------- CSR build ----------------
__global__ void zero_int_kernel(int* __restrict__ p, int n) {
    int i = blockIdx.x * blockDim.x + threadIdx.x;
    if (i < n) p[i] = 0;
}

__global__ void hist_kernel(const int* __restrict__ row, const int* __restrict__ col,
                            int* __restrict__ cnt, int E) {
    int e = blockIdx.x * blockDim.x + threadIdx.x;
    if (e < E) {
        int r = row[e], c = col[e];
        if (r != c) atomicAdd(&cnt[r], 1);
    }
}

// scan stage 1 + dinv fused (reads cnt anyway)
__global__ __launch_bounds__(SCAN_B) void scan_sum_kernel(
    const int* __restrict__ cnt, int* __restrict__ bsum, float* __restrict__ dinv, int N)
{
    __shared__ int wsum[SCAN_B / 32];
    int i = blockIdx.x * SCAN_B + threadIdx.x;
    int v = (i < N) ? cnt[i] : 0;
    if (i < N) dinv[i] = (v > 0) ? rsqrtf((float)v) : 0.f;
    int lane = threadIdx.x & 31, w = threadIdx.x >> 5;
#pragma unroll
    for (int o = 16; o > 0; o >>= 1) v += __shfl_down_sync(~0u, v, o);
    if (lane == 0) wsum[w] = v;
    __syncthreads();
    if (threadIdx.x == 0) {
        int s = 0;
#pragma unroll
        for (int j = 0; j < SCAN_B / 32; j++) s += wsum[j];
        bsum[blockIdx.x] = s;
    }
}

__global__ __launch_bounds__(256) void scan_partials_kernel(int* __restrict__ bsum, int nblk)
{
    __shared__ int woff[8];
    int t = threadIdx.x;
    int v = (t < nblk) ? bsum[t] : 0;
    int lane = t & 31, w = t >> 5;
    int x = v;
#pragma unroll
    for (int o = 1; o < 32; o <<= 1) {
        int y = __shfl_up_sync(~0u, x, o);
        if (lane >= o) x += y;
    }
    if (lane == 31) woff[w] = x;
    __syncthreads();
    if (t == 0) {
        int run = 0;
#pragma unroll
        for (int j = 0; j < 8; j++) { int tmp = woff[j]; woff[j] = run; run += tmp; }
    }
    __syncthreads();
    int excl = x - v + woff[w];
    if (t < nblk) bsum[t] = excl;
}

__global__ __launch_bounds__(SCAN_B) void scan_write_kernel(
    const int* __restrict__ cnt, const int* __restrict__ bsum,
    int* __restrict__ rowptr, int* __restrict__ cur, int N)
{
    __shared__ int woff[SCAN_B / 32];
    int t = threadIdx.x;
    int i = blockIdx.x * SCAN_B + t;
    int v = (i < N) ? cnt[i] : 0;
    int lane = t & 31, w = t >> 5;
    int x = v;
#pragma unroll
    for (int o = 1; o < 32; o <<= 1) {
        int y = __shfl_up_sync(~0u, x, o);
        if (lane >= o) x += y;
    }
    if (lane == 31) woff[w] = x;
    __syncthreads();
    if (t == 0) {
        int run = 0;
#pragma unroll
        for (int j = 0; j < SCAN_B / 32; j++) { int tmp = woff[j]; woff[j] = run; run += tmp; }
    }
    __syncthreads();
    int excl = x - v + woff[w] + bsum[blockIdx.x];
    if (i < N) { rowptr[i] = excl; cur[i] = excl; }
    if (i == N - 1) rowptr[N] = excl + v;
}

__global__ void scatter_kernel(const int* __restrict__ row, const int* __restrict__ col,
                               const float* __restrict__ dinv,
                               int* __restrict__ cur, int2* __restrict__ ecw, int E)
{
    int e = blockIdx.x * blockDim.x + threadIdx.x;
    if (e < E) {
        int r = row[e], c = col[e];
        if (r != c) {
            int pos = atomicAdd(&cur[r], 1);
            float w = -dinv[r] * dinv[c];
            ecw[pos] = make_int2(c, __float_as_int(w));
        }
    }
}

// Combined weight [gk][n], gk = p*128 + din: {W0-W2, W1, 2*W2}; bf16 hi/lo, all 3 layers.
__global__ void prep_wbf_all_kernel(const float* __restrict__ Wa, const float* __restrict__ Wb,
                                    const float* __restrict__ Wc,
                                    __nv_bfloat16* __restrict__ Bhi,
                                    __nv_bfloat16* __restrict__ Blo) {
    int t = blockIdx.x * blockDim.x + threadIdx.x;   // over 3 * 384*128
    if (t < 3 * 3 * D * D) {
        int layer = t / (3 * D * D);
        int idx   = t % (3 * D * D);
        const float* W = (layer == 0) ? Wa : (layer == 1) ? Wb : Wc;
        int gk = idx / D;
        int n  = idx % D;
        int p  = gk >> 7;
        int din = gk & 127;
        float v;
        if (p == 0)      v = W[din * D + n] - W[2 * D * D + din * D + n];
        else if (p == 1) v = W[D * D + din * D + n];
        else             v = 2.f * W[2 * D * D + din * D + n];
        __nv_bfloat16 hi = __float2bfloat16(v);
        __nv_bfloat16 lo = __float2bfloat16(v - __bfloat162float(hi));
        Bhi[t] = hi;
        Blo[t] = lo;
    }
}

// ---------------- atomic-free propagation (unchanged, validated) ----------------
__global__ __launch_bounds__(256) void prop_csr_kernel(
    const float* __restrict__ src, float* __restrict__ dst,
    const int* __restrict__ rowptr, const int2* __restrict__ ecw, int N)
{
    const int warp = (blockIdx.x * blockDim.x + threadIdx.x) >> 5;
    const int lane = threadIdx.x & 31;
    if (warp >= N) return;

    const int s = __ldg(rowptr + warp);
    const int e = __ldg(rowptr + warp + 1);

    float ax = 0.f, ay = 0.f, az = 0.f, aw = 0.f;
    const int off = lane * 4;

    int i = s;
    for (; i + 3 < e; i += 4) {
        int2 e0 = __ldg(ecw + i);
        int2 e1 = __ldg(ecw + i + 1);
        int2 e2 = __ldg(ecw + i + 2);
        int2 e3 = __ldg(ecw + i + 3);
        float4 v0 = *reinterpret_cast<const float4*>(src + (size_t)e0.x * D + off);
        float4 v1 = *reinterpret_cast<const float4*>(src + (size_t)e1.x * D + off);
        float4 v2 = *reinterpret_cast<const float4*>(src + (size_t)e2.x * D + off);
        float4 v3 = *reinterpret_cast<const float4*>(src + (size_t)e3.x * D + off);
        float w0 = __int_as_float(e0.y), w1 = __int_as_float(e1.y);
        float w2 = __int_as_float(e2.y), w3 = __int_as_float(e3.y);
        ax = fmaf(w0, v0.x, ax); ay = fmaf(w0, v0.y, ay);
        az = fmaf(w0, v0.z, az); aw = fmaf(w0, v0.w, aw);
        ax = fmaf(w1, v1.x, ax); ay = fmaf(w1, v1.y, ay);
        az = fmaf(w1, v1.z, az); aw = fmaf(w1, v1.w, aw);
        ax = fmaf(w2, v2.x, ax); ay = fmaf(w2, v2.y, ay);
        az = fmaf(w2, v2.z, az); aw = fmaf(w2, v2.w, aw);
        ax = fmaf(w3, v3.x, ax); ay = fmaf(w3, v3.y, ay);
        az = fmaf(w3, v3.z, az); aw = fmaf(w3, v3.w, aw);
    }
    for (; i < e; ++i) {
        int2 e0 = __ldg(ecw + i);
        float w0 = __int_as_float(e0.y);
        float4 v0 = *reinterpret_cast<const float4*>(src + (size_t)e0.x * D + off);
        ax = fmaf(w0, v0.x, ax); ay = fmaf(w0, v0.y, ay);
        az = fmaf(w0, v0.z, az); aw = fmaf(w0, v0.w, aw);
    }

    *reinterpret_cast<float4*>(dst + (size_t)warp * D + off) = make_float4(ax, ay, az, aw);
}

// ---------------- wmma bf16-split fused triple GEMM + bias + ReLU ----------------
// REVERTED to validated 128x128 CTA / 32x64 warp tile (round-12, 457.7us), plus:
//  - accumulators initialized with bias (smem broadcast tile -> load_matrix_sync)
//  - ReLU applied elementwise on accumulator fragments
//  - full blocks store fragments DIRECTLY to gmem (no smem staging round-trip);
//    only the ragged tail block uses the staged path (block-uniform branch).
#define LDA 40
#define LDB 136
#define LDC 132
#define A_BUF_B (128 * LDA * 2)               // 10240
#define B_BUF_B (32 * LDB * 2)                // 8704
#define SM_AHI(s)  ((s) * (2 * A_BUF_B + 2 * B_BUF_B))
#define SM_ALO(s)  (SM_AHI(s) + A_BUF_B)
#define SM_BHI(s)  (SM_ALO(s) + A_BUF_B)
#define SM_BLO(s)  (SM_BHI(s) + B_BUF_B)
#define SM_AB_END  (2 * (2 * A_BUF_B + 2 * B_BUF_B))   // 75776
#define SM_STAGE_BYTES (128 * LDC * 4)                 // 67584 (tail block only, aliased)
#define SM_TOTAL (SM_AB_END > SM_STAGE_BYTES ? SM_AB_END : SM_STAGE_BYTES)

__global__ __launch_bounds__(256) void gemm3_wmma_kernel(
    const float* __restrict__ A0, const float* __restrict__ A1, const float* __restrict__ A2,
    const __nv_bfloat16* __restrict__ Whi, const __nv_bfloat16* __restrict__ Wlo,
    const float* __restrict__ bias, float* __restrict__ out, int nrows)
{
    extern __shared__ char smem[];
    float* sF = reinterpret_cast<float*>(smem);   // bias init region / tail staging

    const int tid = threadIdx.x;
    const int wid = tid >> 5;
    const int wm  = wid & 3;
    const int wn  = wid >> 2;
    const int row0 = blockIdx.x * 128;

    const int a_row  = tid >> 1;
    const int a_c0   = (tid & 1) * 16;
    const int grow   = row0 + a_row;
    const bool valid = (grow < nrows);
    const int b_row = tid >> 3;
    const int b_c0  = (tid & 7) * 16;

    // ---- init accumulators with bias (16x128 smem tile, rows replicated) ----
    wmma::fragment<wmma::accumulator, 16, 16, 16, float> acc[2][4];
    {
#pragma unroll
        for (int q = 0; q < 2; ++q) {
            int t = tid + q * 256;            // 0..511 over 16 rows x 32 float4
            int brow = t >> 5;
            int c4   = (t & 31) * 4;
            *reinterpret_cast<float4*>(sF + brow * LDC + c4) =
                *reinterpret_cast<const float4*>(bias + c4);
        }
        __syncthreads();
#pragma unroll
        for (int i = 0; i < 2; i++)
#pragma unroll
            for (int j = 0; j < 4; j++)
                wmma::load_matrix_sync(acc[i][j], sF + wn * 64 + j * 16, LDC,
                                       wmma::mem_row_major);
        __syncthreads();
    }

    float4 ra[4];
    uint4  rb[4];
    auto fetch = [&](int ch) {
        const int part  = ch >> 2;
        const float* A  = (part == 0) ? A0 : (part == 1) ? A1 : A2;
        const int kbase = (ch & 3) * 32;
#pragma unroll
        for (int q = 0; q < 4; ++q) {
            ra[q] = make_float4(0.f, 0.f, 0.f, 0.f);
            if (valid)
                ra[q] = *reinterpret_cast<const float4*>(A + (size_t)grow * D + kbase + a_c0 + q * 4);
        }
        const size_t g = (size_t)(ch * 32 + b_row) * D + b_c0;
        rb[0] = *reinterpret_cast<const uint4*>(Whi + g);
        rb[1] = *reinterpret_cast<const uint4*>(Whi + g + 8);
        rb[2] = *reinterpret_cast<const uint4*>(Wlo + g);
        rb[3] = *reinterpret_cast<const uint4*>(Wlo + g + 8);
    };
    auto stash = [&](int s) {
        __nv_bfloat16* sAhi = reinterpret_cast<__nv_bfloat16*>(smem + SM_AHI(s));
        __nv_bfloat16* sAlo = reinterpret_cast<__nv_bfloat16*>(smem + SM_ALO(s));
        __nv_bfloat16* sBhi = reinterpret_cast<__nv_bfloat16*>(smem + SM_BHI(s));
        __nv_bfloat16* sBlo = reinterpret_cast<__nv_bfloat16*>(smem + SM_BLO(s));
#pragma unroll
        for (int q = 0; q < 4; ++q) {
            const int c = a_c0 + q * 4;
            float4 v = ra[q];
            __nv_bfloat162 h01 = __floats2bfloat162_rn(v.x, v.y);
            __nv_bfloat162 h23 = __floats2bfloat162_rn(v.z, v.w);
            __nv_bfloat162 l01 = __floats2bfloat162_rn(v.x - __bfloat162float(h01.x),
                                                       v.y - __bfloat162float(h01.y));
            __nv_bfloat162 l23 = __floats2bfloat162_rn(v.z - __bfloat162float(h23.x),
                                                       v.w - __bfloat162float(h23.y));
            *reinterpret_cast<__nv_bfloat162*>(sAhi + a_row * LDA + c)     = h01;
            *reinterpret_cast<__nv_bfloat162*>(sAhi + a_row * LDA + c + 2) = h23;
            *reinterpret_cast<__nv_bfloat162*>(sAlo + a_row * LDA + c)     = l01;
            *reinterpret_cast<__nv_bfloat162*>(sAlo + a_row * LDA + c + 2) = l23;
        }
        *reinterpret_cast<uint4*>(sBhi + b_row * LDB + b_c0)     = rb[0];
        *reinterpret_cast<uint4*>(sBhi + b_row * LDB + b_c0 + 8) = rb[1];
        *reinterpret_cast<uint4*>(sBlo + b_row * LDB + b_c0)     = rb[2];
        *reinterpret_cast<uint4*>(sBlo + b_row * LDB + b_c0 + 8) = rb[3];
    };

    fetch(0);
    stash(0);
    __syncthreads();

    for (int ch = 0; ch < 12; ++ch) {
        const int cur = ch & 1;
        if (ch + 1 < 12) fetch(ch + 1);   // overlap gmem with mma below

        const __nv_bfloat16* sAhi = reinterpret_cast<const __nv_bfloat16*>(smem + SM_AHI(cur));
        const __nv_bfloat16* sAlo = reinterpret_cast<const __nv_bfloat16*>(smem + SM_ALO(cur));
        const __nv_bfloat16* sBhi = reinterpret_cast<const __nv_bfloat16*>(smem + SM_BHI(cur));
        const __nv_bfloat16* sBlo = reinterpret_cast<const __nv_bfloat16*>(smem + SM_BLO(cur));

#pragma unroll
        for (int k16 = 0; k16 < 2; ++k16) {
            wmma::fragment<wmma::matrix_a, 16, 16, 16, __nv_bfloat16, wmma::row_major> fahi[2], falo[2];
            wmma::fragment<wmma::matrix_b, 16, 16, 16, __nv_bfloat16, wmma::row_major> fbhi[4], fblo[4];
#pragma unroll
            for (int i = 0; i < 2; i++) {
                wmma::load_matrix_sync(fahi[i], sAhi + (wm * 32 + i * 16) * LDA + k16 * 16, LDA);
                wmma::load_matrix_sync(falo[i], sAlo + (wm * 32 + i * 16) * LDA + k16 * 16, LDA);
            }
#pragma unroll
            for (int j = 0; j < 4; j++) {
                wmma::load_matrix_sync(fbhi[j], sBhi + (k16 * 16) * LDB + wn * 64 + j * 16, LDB);
                wmma::load_matrix_sync(fblo[j], sBlo + (k16 * 16) * LDB + wn * 64 + j * 16, LDB);
            }
#pragma unroll
            for (int i = 0; i < 2; i++)
#pragma unroll
                for (int j = 0; j < 4; j++) {
                    wmma::mma_sync(acc[i][j], fahi[i], fbhi[j], acc[i][j]);
                    wmma::mma_sync(acc[i][j], fahi[i], fblo[j], acc[i][j]);
                    wmma::mma_sync(acc[i][j], falo[i], fbhi[j], acc[i][j]);
                }
        }

        if (ch + 1 < 12) {
            stash((ch + 1) & 1);   // writes other buffer; readers above used cur
            __syncthreads();
        }
    }

    // ---- ReLU on fragments (bias already inside) ----
#pragma unroll
    for (int i = 0; i < 2; i++)
#pragma unroll
        for (int j = 0; j < 4; j++)
#pragma unroll
            for (int t = 0; t < acc[i][j].num_elements; t++)
                acc[i][j].x[t] = fmaxf(acc[i][j].x[t], 0.f);

    if (row0 + 128 <= nrows) {
        // full block: store fragments directly to gmem (no staging)
#pragma unroll
        for (int i = 0; i < 2; i++)
#pragma unroll
            for (int j = 0; j < 4; j++)
                wmma::store_matrix_sync(out + (size_t)(row0 + wm * 32 + i * 16) * D + wn * 64 + j * 16,
                                        acc[i][j], D, wmma::mem_row_major);
    } else {
        // ragged tail block (block-uniform branch): stage, then copy valid rows
        __syncthreads();   // mainloop smem reads done before aliasing
#pragma unroll
        for (int i = 0; i < 2; i++)
#pragma unroll
            for (int j = 0; j < 4; j++)
                wmma::store_matrix_sync(sF + (wm * 32 + i * 16) * LDC + wn * 64 + j * 16,
                                        acc[i][j], LDC, wmma::mem_row_major);
        __syncthreads();
        const int r  = row0 + (tid >> 1);
        const int c0 = (tid & 1) * 64;
        if (r < nrows) {
            const float* src = sF + (tid >> 1) * LDC + c0;
            float* dst = out + (size_t)r * D + c0;
#pragma unroll
            for (int q = 0; q < 16; ++q)
                *reinterpret_cast<float4*>(dst + q * 4) =
                    *reinterpret_cast<const float4*>(src + q * 4);
        }
    }
}

// ---------------- host-side orchestration ----------------
static inline int ceil_div(int a, int b) { return (a + b - 1) / b; }

extern "C" void kernel_launch(void* const* d_in, const int* in_sizes, int n_in,
                              void* d_out, int out_size)
{
    const float* x  = (const float*)d_in[0];
    const int*   ei = (const int*)  d_in[1];
    const float* W1 = (const float*)d_in[2];
    const float* b1 = (const float*)d_in[3];
    const float* W2 = (const float*)d_in[4];
    const float* b2 = (const float*)d_in[5];
    const float* W3 = (const float*)d_in[6];
    const float* b3 = (const float*)d_in[7];
    float* out = (float*)d_out;

    const int N = in_sizes[0] / D;
    const int E = in_sizes[1] / 2;
    const int* row = ei;
    const int* col = ei + E;

    float *T1, *P, *Ha, *Hb, *dinv;
    __nv_bfloat16 (*Whi)[3 * D * D], (*Wlo)[3 * D * D];
    int *cnt, *rowptr, *cur, *bsum;
    int2* ecw;
    cudaGetSymbolAddress((void**)&T1,     g_T1);
    cudaGetSymbolAddress((void**)&P,      g_P);
    cudaGetSymbolAddress((void**)&Ha,     g_Ha);
    cudaGetSymbolAddress((void**)&Hb,     g_Hb);
    cudaGetSymbolAddress((void**)&Whi,    g_Wbhi);
    cudaGetSymbolAddress((void**)&Wlo,    g_Wblo);
    cudaGetSymbolAddress((void**)&dinv,   g_dinv);
    cudaGetSymbolAddress((void**)&cnt,    g_cnt);
    cudaGetSymbolAddress((void**)&rowptr, g_rowptr);
    cudaGetSymbolAddress((void**)&cur,    g_cur);
    cudaGetSymbolAddress((void**)&ecw,    g_ecw);
    cudaGetSymbolAddress((void**)&bsum,   g_bsum);

    cudaFuncSetAttribute(gemm3_wmma_kernel,
                         cudaFuncAttributeMaxDynamicSharedMemorySize, SM_TOTAL);

    const int egrid = ceil_div(E, 256);
    const int ngrid = ceil_div(N, 256);
    const int sgrid = ceil_div(N, SCAN_B);
    const int pgrid = ceil_div(N * 32, 256);
    const int ggrid = ceil_div(N, 128);

    // ---- weight prep (all 3 layers) ----
    prep_wbf_all_kernel<<<ceil_div(3 * 3 * D * D, 256), 256>>>(W1, W2, W3, Whi[0], Wlo[0]);

    // ---- CSR build (once; serves all 6 props) ----
    zero_int_kernel<<<ngrid, 256>>>(cnt, N);
    hist_kernel<<<egrid, 256>>>(row, col, cnt, E);
    scan_sum_kernel<<<sgrid, SCAN_B>>>(cnt, bsum, dinv, N);
    scan_partials_kernel<<<1, 256>>>(bsum, sgrid);
    scan_write_kernel<<<sgrid, SCAN_B>>>(cnt, bsum, rowptr, cur, N);
    scatter_kernel<<<egrid, 256>>>(row, col, dinv, cur, ecw, E);

    // ---- layer 1 ----
    prop_csr_kernel<<<pgrid, 256>>>(x,  T1, rowptr, ecw, N);
    prop_csr_kernel<<<pgrid, 256>>>(T1, P,  rowptr, ecw, N);
    gemm3_wmma_kernel<<<ggrid, 256, SM_TOTAL>>>(x, T1, P, Whi[0], Wlo[0], b1, Ha, N);

    // ---- layer 2 ----
    prop_csr_kernel<<<pgrid, 256>>>(Ha, T1, rowptr, ecw, N);
    prop_csr_kernel<<<pgrid, 256>>>(T1, P,  rowptr, ecw, N);
    gemm3_wmma_kernel<<<ggrid, 256, SM_TOTAL>>>(Ha, T1, P, Whi[1], Wlo[1], b2, Hb, N);

    // ---- layer 3 ----
    prop_csr_kernel<<<pgrid, 256>>>(Hb, T1, rowptr, ecw, N);
    prop_csr_kernel<<<pgrid, 256>>>(T1, P,  rowptr, ecw, N);
    gemm3_wmma_kernel<<<ggrid, 256, SM_TOTAL>>>(Hb, T1, P, Whi[2], Wlo[2], b3, out, N);
}